// round 14
// baseline (speedup 1.0000x reference)
#include <cuda_runtime.h>
#include <cuda_bf16.h>
#include <mma.h>
#include <cstdint>

using namespace nvcuda;

#define NN 50000
#define EE 1000000
#define DD 64

// extended-K GEMM geometry: [hi|hi|lo] (192) + bias_hi + bias_lo + pad = 208
#define KTOT 208
#define A_LD 216      // bf16 elements per A row in smem
#define B_LD 264      // bf16 elements per B row in smem
#define A_BYTES (128*A_LD*2)          // 55296
#define B_BYTES (KTOT*B_LD*2)         // 109824
#define GEMM_SMEM (A_BYTES + B_BYTES) // 165120
#define S_LD 132      // fp32 stage ld (64-row half, lives in A region)
#define GEMM_GRID 152 // persistent CTAs (GB300: 152 SMs)
#define NRB ((NN + 127) / 128)        // 391 row blocks
#define ATTN_GRID (152*6)             // persistent attention CTAs

#define NCHUNK 49     // ceil(NN/1024)

// ---------------- scratch (device globals; no allocation allowed) ----------
__device__ float g_bufA[NN*DD];
__device__ float g_bufB[NN*DD];
__device__ float g_q [NN*DD];
__device__ float g_sk[NN*DD];
__device__ __nv_bfloat16 g_kb[NN*DD];
__device__ __nv_bfloat16 g_vb[NN*DD];
__device__ int   g_deg[NN];
__device__ int   g_rowptr[NN+1];
__device__ int   g_cursor[NN];
__device__ int   g_csrc[EE];
__device__ int   g_bsum[64];
__device__ int   g_boff[64];
// prepped weights: 4 layer-sets x [KTOT rows x 256 cols] bf16
__device__ __nv_bfloat16 g_Wb[4*KTOT*256];

// ---------------- CSR build (by dst) ---------------------------------------
__global__ void k_zero_deg(){
    int i = blockIdx.x*blockDim.x + threadIdx.x;
    if (i < NN) g_deg[i] = 0;
}
__global__ void k_hist(const int4* __restrict__ dst4){
    int i = blockIdx.x*blockDim.x + threadIdx.x;
    if (i < EE/4){
        int4 d = dst4[i];
        atomicAdd(&g_deg[d.x], 1);
        atomicAdd(&g_deg[d.y], 1);
        atomicAdd(&g_deg[d.z], 1);
        atomicAdd(&g_deg[d.w], 1);
    }
}
// 3-phase parallel scan ------------------------------------------------------
__global__ void k_scan1(){
    __shared__ int wsum[32];
    int b = blockIdx.x, t = threadIdx.x, lane = t & 31, w = t >> 5;
    int i = b*1024 + t;
    int v = (i < NN) ? g_deg[i] : 0;
    int x = v;
    #pragma unroll
    for (int off = 1; off < 32; off <<= 1){
        int y = __shfl_up_sync(0xffffffffu, x, off);
        if (lane >= off) x += y;
    }
    if (lane == 31) wsum[w] = x;
    __syncthreads();
    if (w == 0){
        int s = wsum[lane];
        #pragma unroll
        for (int off = 1; off < 32; off <<= 1){
            int y = __shfl_up_sync(0xffffffffu, s, off);
            if (lane >= off) s += y;
        }
        wsum[lane] = s;
    }
    __syncthreads();
    int incl = x + ((w > 0) ? wsum[w-1] : 0);
    if (i < NN) g_rowptr[i] = incl - v;       // local exclusive
    if (t == 1023) g_bsum[b] = incl;          // block total
}
__global__ void k_scan2(){
    __shared__ int s[64];
    int t = threadIdx.x;
    int v = (t < NCHUNK) ? g_bsum[t] : 0;
    s[t] = v;
    __syncthreads();
    #pragma unroll
    for (int off = 1; off < 64; off <<= 1){
        int y = (t >= off) ? s[t-off] : 0;
        __syncthreads();
        s[t] += y;
        __syncthreads();
    }
    g_boff[t] = s[t] - v;                     // exclusive
    if (t == 63) g_rowptr[NN] = s[63];        // grand total
}
__global__ void k_scan3(){
    int i = blockIdx.x*1024 + threadIdx.x;
    if (i < NN){
        int r = g_rowptr[i] + g_boff[blockIdx.x];
        g_rowptr[i] = r;
        g_cursor[i] = r;
    }
}
__global__ void k_scatter(const int* __restrict__ src, const int* __restrict__ dst){
    int e = blockIdx.x*blockDim.x + threadIdx.x;
    if (e < EE){
        int pos = atomicAdd(&g_cursor[dst[e]], 1);
        g_csrc[pos] = src[e];
    }
}

// ---------------- weight prep ------------------------------------------------
// g_Wb[l] rows: [0,64)=W_hi, [64,128)=W_lo, [128,192)=W_hi, 192=bias_hi,
// 193=bias_lo, [194,208)=0. Cols: mat*64+nc for mat in {q,k,v,s}.
// NOTE: mat 0 (q) weights+bias are pre-scaled by 0.125 (= 1/sqrt(D)).
__global__ void k_prep(
    const float* __restrict__ Wq0, const float* __restrict__ Wk0,
    const float* __restrict__ Wv0, const float* __restrict__ Ws0,
    const float* __restrict__ Wq,  const float* __restrict__ Wk,
    const float* __restrict__ Wv,  const float* __restrict__ Ws,
    const float* __restrict__ bq0, const float* __restrict__ bk0,
    const float* __restrict__ bv0, const float* __restrict__ bs0,
    const float* __restrict__ bq,  const float* __restrict__ bk,
    const float* __restrict__ bv,  const float* __restrict__ bs)
{
    int gid = blockIdx.x*256 + threadIdx.x;
    if (gid >= 4*KTOT*256) return;
    int l   = gid / (KTOT*256);
    int rem = gid - l*(KTOT*256);
    int kk  = rem >> 8;
    int n   = rem & 255;
    int mat = n >> 6;
    int nc  = n & 63;

    __nv_bfloat16 out = __float2bfloat16_rn(0.f);
    if (kk < 192){
        int k   = kk & 63;
        int reg = kk >> 6;       // 0:hi 1:lo 2:hi
        const float* W;
        if (l == 0){
            W = (mat==0)?Wq0:(mat==1)?Wk0:(mat==2)?Wv0:Ws0;
        } else {
            const float* Wb_ = (mat==0)?Wq:(mat==1)?Wk:(mat==2)?Wv:Ws;
            W = Wb_ + (l-1)*DD*DD;
        }
        float x = W[k*64 + nc];
        if (mat == 0) x *= 0.125f;
        __nv_bfloat16 hi = __float2bfloat16_rn(x);
        if (reg == 1) out = __float2bfloat16_rn(x - __bfloat162float(hi));
        else          out = hi;
    } else if (kk == 192 || kk == 193){
        const float* b;
        if (l == 0){
            b = (mat==0)?bq0:(mat==1)?bk0:(mat==2)?bv0:bs0;
        } else {
            const float* bb = (mat==0)?bq:(mat==1)?bk:(mat==2)?bv:bs;
            b = bb + (l-1)*DD;
        }
        float x = b[nc];
        if (mat == 0) x *= 0.125f;
        __nv_bfloat16 hi = __float2bfloat16_rn(x);
        if (kk == 193) out = __float2bfloat16_rn(x - __bfloat162float(hi));
        else           out = hi;
    }
    g_Wb[(size_t)l*KTOT*256 + kk*256 + n] = out;
}

// ---------------- gemm helper phases ----------------------------------------
__device__ __forceinline__ void gemm_copyB(
    __nv_bfloat16* Bs, const __nv_bfloat16* __restrict__ Wb, int t)
{
    const uint4* gB = reinterpret_cast<const uint4*>(Wb);
    for (int i = t; i < 6656; i += 256){
        int r  = i >> 5;
        int c8 = (i & 31) << 3;
        *(uint4*)(Bs + r*B_LD + c8) = gB[i];
    }
}
__device__ __forceinline__ void gemm_fillA(
    __nv_bfloat16* As, const float* __restrict__ h, int t, int row0)
{
    #pragma unroll
    for (int i = 0; i < 8; i++){
        int idx = t + i*256;          // 0..2047 -> (r, c4)
        int r = idx >> 4, c4 = (idx & 15) * 4;
        float4 v = make_float4(0.f,0.f,0.f,0.f);
        if (row0 + r < NN) v = reinterpret_cast<const float4*>(h)[(row0+r)*16 + (c4>>2)];
        __nv_bfloat16 h0 = __float2bfloat16_rn(v.x);
        __nv_bfloat16 h1 = __float2bfloat16_rn(v.y);
        __nv_bfloat16 h2 = __float2bfloat16_rn(v.z);
        __nv_bfloat16 h3 = __float2bfloat16_rn(v.w);
        __nv_bfloat16 l0 = __float2bfloat16_rn(v.x - __bfloat162float(h0));
        __nv_bfloat16 l1 = __float2bfloat16_rn(v.y - __bfloat162float(h1));
        __nv_bfloat16 l2 = __float2bfloat16_rn(v.z - __bfloat162float(h2));
        __nv_bfloat16 l3 = __float2bfloat16_rn(v.w - __bfloat162float(h3));
        uint32_t hA = ((uint32_t)__bfloat16_as_ushort(h1) << 16) | __bfloat16_as_ushort(h0);
        uint32_t hB = ((uint32_t)__bfloat16_as_ushort(h3) << 16) | __bfloat16_as_ushort(h2);
        uint32_t lA = ((uint32_t)__bfloat16_as_ushort(l1) << 16) | __bfloat16_as_ushort(l0);
        uint32_t lB = ((uint32_t)__bfloat16_as_ushort(l3) << 16) | __bfloat16_as_ushort(l2);
        __nv_bfloat16* Ar = As + r*A_LD;
        *(uint2*)(Ar + c4)       = make_uint2(hA, hB);
        *(uint2*)(Ar + 64 + c4)  = make_uint2(hA, hB);
        *(uint2*)(Ar + 128 + c4) = make_uint2(lA, lB);
    }
}
__device__ __forceinline__ void gemm_tailA(__nv_bfloat16* As, int t)
{
    __nv_bfloat16 one  = __float2bfloat16_rn(1.0f);
    __nv_bfloat16 zero = __float2bfloat16_rn(0.0f);
    for (int idx = t; idx < 128*24; idx += 256){
        int r = idx / 24, c = idx - r*24;
        As[r*A_LD + 192 + c] = (c < 2) ? one : zero;
    }
}

// ---------------- persistent wmma bf16 fused 4-way GEMM (PDL) ----------------
__global__ void __launch_bounds__(256) k_gemm_wmma(
    const float* __restrict__ h,
    const __nv_bfloat16* __restrict__ Wb,
    int ext)
{
    extern __shared__ char sm[];
    __nv_bfloat16* As = (__nv_bfloat16*)sm;
    __nv_bfloat16* Bs = (__nv_bfloat16*)(sm + A_BYTES);
    float* stage = (float*)sm;     // 64-row k/v stage, aliases A region

    cudaTriggerProgrammaticLaunchCompletion();

    int t = threadIdx.x;
    int w = t >> 5;
    int rbase = (w & 3) * 32;
    int cbase = (w >> 2) * 128;
    int half_of_warp = (w & 3) >> 1;   // rbase 0,32 -> 0; 64,96 -> 1

    if (ext){
        gemm_fillA(As, h, t, blockIdx.x*128);
        gemm_tailA(As, t);
        cudaGridDependencySynchronize();
        gemm_copyB(Bs, Wb, t);
    } else {
        gemm_copyB(Bs, Wb, t);
        cudaGridDependencySynchronize();
    }

    for (int rb = blockIdx.x; rb < NRB; rb += gridDim.x){
        int row0 = rb*128;
        if (!(ext && rb == blockIdx.x)){
            __syncthreads();           // prior block's stage reads done
            gemm_fillA(As, h, t, row0);
            gemm_tailA(As, t);
        }
        __syncthreads();

        wmma::fragment<wmma::accumulator, 16,16,16, float> acc[2][8];
        #pragma unroll
        for (int i = 0; i < 2; i++)
            #pragma unroll
            for (int j = 0; j < 8; j++) wmma::fill_fragment(acc[i][j], 0.f);

        #pragma unroll
        for (int k = 0; k < KTOT; k += 16){
            wmma::fragment<wmma::matrix_a, 16,16,16, __nv_bfloat16, wmma::row_major> a0, a1;
            wmma::load_matrix_sync(a0, As + (rbase     )*A_LD + k, A_LD);
            wmma::load_matrix_sync(a1, As + (rbase + 16)*A_LD + k, A_LD);
            #pragma unroll
            for (int ct = 0; ct < 8; ct++){
                wmma::fragment<wmma::matrix_b, 16,16,16, __nv_bfloat16, wmma::row_major> b;
                wmma::load_matrix_sync(b, Bs + k*B_LD + cbase + ct*16, B_LD);
                wmma::mma_sync(acc[0][ct], a0, b, acc[0][ct]);
                wmma::mma_sync(acc[1][ct], a1, b, acc[1][ct]);
            }
        }

        // --- pass 1: q (mat0) and sk (mat3) straight to global fp32 --------
        #pragma unroll
        for (int rt = 0; rt < 2; rt++){
            int grow = row0 + rbase + rt*16;
            if (grow >= NN) continue;  // NN % 16 == 0: tiles never straddle
            #pragma unroll
            for (int ct = 0; ct < 8; ct++){
                int gc  = cbase + ct*16;
                int mat = gc >> 6, mc = gc & 63;
                if (mat == 0)
                    wmma::store_matrix_sync(g_q + (size_t)grow*64 + mc,
                                            acc[rt][ct], 64, wmma::mem_row_major);
                else if (mat == 3)
                    wmma::store_matrix_sync(g_sk + (size_t)grow*64 + mc,
                                            acc[rt][ct], 64, wmma::mem_row_major);
            }
        }
        __syncthreads();   // all MMA reads of As complete before staging

        // --- pass 2: k (mat1) / v (mat2) via A-region stage, 2 half-passes --
        #pragma unroll
        for (int half = 0; half < 2; half++){
            if (half_of_warp == half){
                #pragma unroll
                for (int rt = 0; rt < 2; rt++){
                    #pragma unroll
                    for (int ct = 0; ct < 8; ct++){
                        int gc  = cbase + ct*16;
                        int mat = gc >> 6;
                        if (mat == 1 || mat == 2)
                            wmma::store_matrix_sync(
                                stage + (rbase - half*64 + rt*16)*S_LD + (gc - 64),
                                acc[rt][ct], S_LD, wmma::mem_row_major);
                    }
                }
            }
            __syncthreads();
            #pragma unroll
            for (int i = 0; i < 8; i++){
                int idx = t + i*256;
                int r = idx >> 5, c4 = (idx & 31) * 4;
                int row = row0 + half*64 + r;
                if (row < NN){
                    float4 f = *(float4*)(stage + r*S_LD + c4);
                    uint32_t p0 = ((uint32_t)__bfloat16_as_ushort(__float2bfloat16_rn(f.y)) << 16)
                                |  __bfloat16_as_ushort(__float2bfloat16_rn(f.x));
                    uint32_t p1 = ((uint32_t)__bfloat16_as_ushort(__float2bfloat16_rn(f.w)) << 16)
                                |  __bfloat16_as_ushort(__float2bfloat16_rn(f.z));
                    __nv_bfloat16* dp = (c4 < 64) ? (g_kb + (size_t)row*64 + c4)
                                                  : (g_vb + (size_t)row*64 + (c4 - 64));
                    *(uint2*)dp = make_uint2(p0, p1);
                }
            }
            __syncthreads();
        }
    }
}

// ---------------- persistent attention + skip + residual + LN + ReLU (PDL) --
// Each warp strides over ~7 nodes (912 CTAs x 8 warps) -> Poisson degree
// variance averages out; no block-retire quantization, no partial last wave.
// Inner loop is the proven R10 form (4 edges/iter, src-index prefetch).
__global__ void __launch_bounds__(256) k_attn(
    const float* __restrict__ hres,
    const float* __restrict__ gamma, const float* __restrict__ beta,
    float* __restrict__ out, int addres)
{
    cudaTriggerProgrammaticLaunchCompletion();
    cudaGridDependencySynchronize();

    int lane = threadIdx.x & 31;
    int g = lane >> 3;           // edge slot 0..3
    int s = lane & 7;            // dim slice: dims [s*8, s*8+8)
    int warp0  = (blockIdx.x*blockDim.x + threadIdx.x) >> 5;
    int wstride = (gridDim.x*blockDim.x) >> 5;

    const float4* q4  = reinterpret_cast<const float4*>(g_q);
    const float4* sk4 = reinterpret_cast<const float4*>(g_sk);
    const float4* gm4 = reinterpret_cast<const float4*>(gamma);
    const float4* bt4 = reinterpret_cast<const float4*>(beta);
    float4 ga0 = gm4[s*2], ga1 = gm4[s*2+1];
    float4 be0 = bt4[s*2], be1 = bt4[s*2+1];

    for (int node = warp0; node < NN; node += wstride){
        int start = g_rowptr[node];
        int end   = g_rowptr[node+1];

        float4 q0 = q4[node*16 + s*2];
        float4 q1 = q4[node*16 + s*2 + 1];

        float ssum = 0.f;
        float acc[8];
        #pragma unroll
        for (int i=0;i<8;i++) acc[i]=0.f;

        bool valid = (start + g) < end;
        int  src   = valid ? g_csrc[start + g] : 0;

        for (int j0 = start; j0 < end; j0 += 4){
            uint4 kw = *(const uint4*)(g_kb + (size_t)src*64 + s*8);
            uint4 vw = *(const uint4*)(g_vb + (size_t)src*64 + s*8);

            int  jn     = j0 + 4 + g;
            bool validn = jn < end;
            int  srcn   = validn ? g_csrc[jn] : 0;

            float2 k0 = __bfloat1622float2(*(__nv_bfloat162*)&kw.x);
            float2 k1 = __bfloat1622float2(*(__nv_bfloat162*)&kw.y);
            float2 k2 = __bfloat1622float2(*(__nv_bfloat162*)&kw.z);
            float2 k3 = __bfloat1622float2(*(__nv_bfloat162*)&kw.w);
            float p = q0.x*k0.x + q0.y*k0.y + q0.z*k1.x + q0.w*k1.y
                    + q1.x*k2.x + q1.y*k2.y + q1.z*k3.x + q1.w*k3.y;
            p += __shfl_xor_sync(0xffffffffu, p, 1);
            p += __shfl_xor_sync(0xffffffffu, p, 2);
            p += __shfl_xor_sync(0xffffffffu, p, 4);

            float e = valid ? __expf(fminf(p, 80.f)) : 0.f;
            ssum += e;

            float2 v0 = __bfloat1622float2(*(__nv_bfloat162*)&vw.x);
            float2 v1 = __bfloat1622float2(*(__nv_bfloat162*)&vw.y);
            float2 v2 = __bfloat1622float2(*(__nv_bfloat162*)&vw.z);
            float2 v3 = __bfloat1622float2(*(__nv_bfloat162*)&vw.w);
            acc[0] += e*v0.x;
            acc[1] += e*v0.y;
            acc[2] += e*v1.x;
            acc[3] += e*v1.y;
            acc[4] += e*v2.x;
            acc[5] += e*v2.y;
            acc[6] += e*v3.x;
            acc[7] += e*v3.y;

            src   = srcn;
            valid = validn;
        }

        #pragma unroll
        for (int i=0;i<8;i++){
            acc[i] += __shfl_xor_sync(0xffffffffu, acc[i], 8);
            acc[i] += __shfl_xor_sync(0xffffffffu, acc[i], 16);
        }
        ssum += __shfl_xor_sync(0xffffffffu, ssum, 8);
        ssum += __shfl_xor_sync(0xffffffffu, ssum, 16);
        float inv = (ssum > 0.f) ? (1.f/ssum) : 0.f;

        float4 s0 = sk4[node*16 + s*2];
        float4 s1 = sk4[node*16 + s*2 + 1];

        float o[8];
        o[0] = acc[0]*inv + s0.x;  o[1] = acc[1]*inv + s0.y;
        o[2] = acc[2]*inv + s0.z;  o[3] = acc[3]*inv + s0.w;
        o[4] = acc[4]*inv + s1.x;  o[5] = acc[5]*inv + s1.y;
        o[6] = acc[6]*inv + s1.z;  o[7] = acc[7]*inv + s1.w;

        if (addres){
            const float4* r4 = reinterpret_cast<const float4*>(hres);
            float4 r0 = r4[node*16 + s*2];
            float4 r1 = r4[node*16 + s*2 + 1];
            o[0]+=r0.x; o[1]+=r0.y; o[2]+=r0.z; o[3]+=r0.w;
            o[4]+=r1.x; o[5]+=r1.y; o[6]+=r1.z; o[7]+=r1.w;
        }

        float sum = 0.f, sq = 0.f;
        #pragma unroll
        for (int i=0;i<8;i++){ sum += o[i]; sq += o[i]*o[i]; }
        sum += __shfl_xor_sync(0xffffffffu, sum, 1);
        sum += __shfl_xor_sync(0xffffffffu, sum, 2);
        sum += __shfl_xor_sync(0xffffffffu, sum, 4);
        sq  += __shfl_xor_sync(0xffffffffu, sq, 1);
        sq  += __shfl_xor_sync(0xffffffffu, sq, 2);
        sq  += __shfl_xor_sync(0xffffffffu, sq, 4);
        float mean = sum * (1.f/64.f);
        float var  = sq  * (1.f/64.f) - mean*mean;
        float rs   = rsqrtf(var + 1e-5f);

        if (g == 0){
            float4* o4 = reinterpret_cast<float4*>(out);
            float4 ra, rb;
            ra.x = fmaxf(0.f, (o[0]-mean)*rs*ga0.x + be0.x);
            ra.y = fmaxf(0.f, (o[1]-mean)*rs*ga0.y + be0.y);
            ra.z = fmaxf(0.f, (o[2]-mean)*rs*ga0.z + be0.z);
            ra.w = fmaxf(0.f, (o[3]-mean)*rs*ga0.w + be0.w);
            rb.x = fmaxf(0.f, (o[4]-mean)*rs*ga1.x + be1.x);
            rb.y = fmaxf(0.f, (o[5]-mean)*rs*ga1.y + be1.y);
            rb.z = fmaxf(0.f, (o[6]-mean)*rs*ga1.z + be1.z);
            rb.w = fmaxf(0.f, (o[7]-mean)*rs*ga1.w + be1.w);
            o4[node*16 + s*2]     = ra;
            o4[node*16 + s*2 + 1] = rb;
        }
    }
}

// ---------------- PDL launch helpers ----------------------------------------
static void launch_gemm_pdl(const float* h, const __nv_bfloat16* wb, int ext){
    cudaLaunchConfig_t cfg = {};
    cfg.gridDim = dim3(GEMM_GRID);
    cfg.blockDim = dim3(256);
    cfg.dynamicSmemBytes = GEMM_SMEM;
    cfg.stream = 0;
    cudaLaunchAttribute at[1];
    at[0].id = cudaLaunchAttributeProgrammaticStreamSerialization;
    at[0].val.programmaticStreamSerializationAllowed = 1;
    cfg.attrs = at;
    cfg.numAttrs = 1;
    cudaLaunchKernelEx(&cfg, k_gemm_wmma, h, wb, ext);
}
static void launch_attn_pdl(const float* hres, const float* gm, const float* bt,
                            float* out, int addres){
    cudaLaunchConfig_t cfg = {};
    cfg.gridDim = dim3(ATTN_GRID);
    cfg.blockDim = dim3(256);
    cfg.dynamicSmemBytes = 0;
    cfg.stream = 0;
    cudaLaunchAttribute at[1];
    at[0].id = cudaLaunchAttributeProgrammaticStreamSerialization;
    at[0].val.programmaticStreamSerializationAllowed = 1;
    cfg.attrs = at;
    cfg.numAttrs = 1;
    cudaLaunchKernelEx(&cfg, k_attn, hres, gm, bt, out, addres);
}

extern "C" void kernel_launch(void* const* d_in, const int* in_sizes, int n_in,
                              void* d_out, int out_size)
{
    const float* x    = (const float*)d_in[0];
    const int*   ei   = (const int*)  d_in[1];
    const float* Wq0  = (const float*)d_in[2];
    const float* bq0  = (const float*)d_in[3];
    const float* Wk0  = (const float*)d_in[4];
    const float* bk0  = (const float*)d_in[5];
    const float* Wv0  = (const float*)d_in[6];
    const float* bv0  = (const float*)d_in[7];
    const float* Ws0  = (const float*)d_in[8];
    const float* bs0  = (const float*)d_in[9];
    const float* ln0g = (const float*)d_in[10];
    const float* ln0b = (const float*)d_in[11];
    const float* Wq   = (const float*)d_in[12];
    const float* bq   = (const float*)d_in[13];
    const float* Wk   = (const float*)d_in[14];
    const float* bk   = (const float*)d_in[15];
    const float* Wv   = (const float*)d_in[16];
    const float* bv   = (const float*)d_in[17];
    const float* Ws   = (const float*)d_in[18];
    const float* bs   = (const float*)d_in[19];
    const float* lng  = (const float*)d_in[20];
    const float* lnb  = (const float*)d_in[21];
    float* out = (float*)d_out;

    const int*  srcp = ei;
    const int*  dstp = ei + EE;
    const int4* dst4 = (const int4*)(ei + EE);

    float *bufA = nullptr, *bufB = nullptr;
    __nv_bfloat16* wb = nullptr;
    cudaGetSymbolAddress((void**)&bufA, g_bufA);
    cudaGetSymbolAddress((void**)&bufB, g_bufB);
    cudaGetSymbolAddress((void**)&wb, g_Wb);

    cudaFuncSetAttribute(k_gemm_wmma, cudaFuncAttributeMaxDynamicSharedMemorySize,
                         GEMM_SMEM);

    // side stream + fork/join events, created once (first call is the
    // non-captured correctness run; capture sees only launches/events)
    static cudaStream_t s2 = nullptr;
    static cudaEvent_t  evF = nullptr, evJ = nullptr;
    if (s2 == nullptr){
        cudaStreamCreateWithFlags(&s2, cudaStreamNonBlocking);
        cudaEventCreateWithFlags(&evF, cudaEventDisableTiming);
        cudaEventCreateWithFlags(&evJ, cudaEventDisableTiming);
    }

    // fork: CSR build on s2; weight prep + first GEMM on main stream
    cudaEventRecord(evF, 0);
    cudaStreamWaitEvent(s2, evF, 0);
    k_zero_deg<<<(NN+1023)/1024, 1024, 0, s2>>>();
    k_hist    <<<(EE/4 + 255)/256, 256, 0, s2>>>(dst4);
    k_scan1   <<<NCHUNK, 1024, 0, s2>>>();
    k_scan2   <<<1, 64, 0, s2>>>();
    k_scan3   <<<NCHUNK, 1024, 0, s2>>>();
    k_scatter <<<(EE + 255)/256, 256, 0, s2>>>(srcp, dstp);
    cudaEventRecord(evJ, s2);

    k_prep<<<(4*KTOT*256 + 255)/256, 256>>>(Wq0, Wk0, Wv0, Ws0, Wq, Wk, Wv, Ws,
                                            bq0, bk0, bv0, bs0, bq, bk, bv, bs);
    // gemm0: PDL with ext=1 — first-block A fill (from harness input x) runs
    // pre-sync; B copy (k_prep output) runs post-gridsync.
    launch_gemm_pdl(x, wb, 1);

    // join: attention needs the CSR
    cudaStreamWaitEvent(0, evJ, 0);

    // layer 0 (input projection, no residual) — PDL vs gemm0
    launch_attn_pdl(x /*unused*/, ln0g, ln0b, bufA, 0);

    // 3 dynamics layers (with residual); final one writes d_out — all PDL
    const float* ins[3]  = {bufA, bufB, bufA};
    float*       outs[3] = {bufB, bufA, out};
    for (int i = 0; i < 3; i++){
        launch_gemm_pdl(ins[i], wb + (size_t)(i+1)*KTOT*256, 0);
        launch_attn_pdl(ins[i], lng + i*DD, lnb + i*DD, outs[i], 1);
    }
}

// round 15
// speedup vs baseline: 1.0753x; 1.0753x over previous
#include <cuda_runtime.h>
#include <cuda_bf16.h>
#include <mma.h>
#include <cstdint>

using namespace nvcuda;

#define NN 50000
#define EE 1000000
#define DD 64

// extended-K GEMM geometry: [hi|hi|lo] (192) + bias_hi + bias_lo + pad = 208
#define KTOT 208
#define A_LD 216      // bf16 elements per A row in smem
#define B_LD 264      // bf16 elements per B row in smem
#define A_BYTES (128*A_LD*2)          // 55296
#define B_BYTES (KTOT*B_LD*2)         // 109824
#define GEMM_SMEM (A_BYTES + B_BYTES) // 165120
#define S_LD 132      // fp32 stage ld (64-row half, lives in A region)
#define GEMM_GRID 152 // persistent CTAs (GB300: 152 SMs)
#define NRB ((NN + 127) / 128)        // 391 row blocks

#define NCHUNK 49     // ceil(NN/1024)

// ---------------- scratch (device globals; no allocation allowed) ----------
__device__ float g_bufA[NN*DD];
__device__ float g_bufB[NN*DD];
__device__ float g_q [NN*DD];
__device__ float g_sk[NN*DD];
__device__ __nv_bfloat16 g_kb[NN*DD];
__device__ __nv_bfloat16 g_vb[NN*DD];
__device__ int   g_deg[NN];           // zero-init; scan1 re-zeroes after use
__device__ int   g_rowptr[NN+1];
__device__ int   g_cursor[NN];
__device__ int   g_csrc[EE];
__device__ int   g_bsum[64];
// prepped weights: 4 layer-sets x [KTOT rows x 256 cols] bf16
__device__ __nv_bfloat16 g_Wb[4*KTOT*256];

// ---------------- CSR build (by dst) ---------------------------------------
// g_deg is zero before every call: zero-initialized at load, and k_scan1
// resets each element after consuming it (deterministic across replays).
__global__ void k_hist(const int4* __restrict__ dst4){
    int i = blockIdx.x*blockDim.x + threadIdx.x;
    if (i < EE/4){
        int4 d = dst4[i];
        atomicAdd(&g_deg[d.x], 1);
        atomicAdd(&g_deg[d.y], 1);
        atomicAdd(&g_deg[d.z], 1);
        atomicAdd(&g_deg[d.w], 1);
    }
}
// phase 1: per-block local exclusive scan -> rowptr(local), block sums;
// also resets g_deg for the next replay.
__global__ void k_scan1(){
    __shared__ int wsum[32];
    int b = blockIdx.x, t = threadIdx.x, lane = t & 31, w = t >> 5;
    int i = b*1024 + t;
    int v = (i < NN) ? g_deg[i] : 0;
    if (i < NN) g_deg[i] = 0;                 // reset for next call
    int x = v;
    #pragma unroll
    for (int off = 1; off < 32; off <<= 1){
        int y = __shfl_up_sync(0xffffffffu, x, off);
        if (lane >= off) x += y;
    }
    if (lane == 31) wsum[w] = x;
    __syncthreads();
    if (w == 0){
        int s = wsum[lane];
        #pragma unroll
        for (int off = 1; off < 32; off <<= 1){
            int y = __shfl_up_sync(0xffffffffu, s, off);
            if (lane >= off) s += y;
        }
        wsum[lane] = s;
    }
    __syncthreads();
    int incl = x + ((w > 0) ? wsum[w-1] : 0);
    if (i < NN) g_rowptr[i] = incl - v;       // local exclusive
    if (t == 1023) g_bsum[b] = incl;          // block total
}
// phase 2+3 fused: every block redundantly scans the 49 block sums in smem
// (cheap), applies its own offset, materializes rowptr/cursor.
__global__ void k_scan3(){
    __shared__ int s[64];
    int t = threadIdx.x;
    if (t < 64) s[t] = (t < NCHUNK) ? g_bsum[t] : 0;
    __syncthreads();
    #pragma unroll
    for (int off = 1; off < 64; off <<= 1){
        int y = (t < 64 && t >= off) ? s[t-off] : 0;
        __syncthreads();
        if (t < 64) s[t] += y;
        __syncthreads();
    }
    int bo = (blockIdx.x > 0) ? s[blockIdx.x - 1] : 0;   // exclusive offset
    int i = blockIdx.x*1024 + t;
    if (i < NN){
        int r = g_rowptr[i] + bo;
        g_rowptr[i] = r;
        g_cursor[i] = r;
    }
    if (blockIdx.x == 0 && t == 0) g_rowptr[NN] = s[63]; // grand total
}
__global__ void k_scatter(const int* __restrict__ src, const int* __restrict__ dst){
    int e = blockIdx.x*blockDim.x + threadIdx.x;
    if (e < EE){
        int pos = atomicAdd(&g_cursor[dst[e]], 1);
        g_csrc[pos] = src[e];
    }
}

// ---------------- weight prep ------------------------------------------------
// g_Wb[l] rows: [0,64)=W_hi, [64,128)=W_lo, [128,192)=W_hi, 192=bias_hi,
// 193=bias_lo, [194,208)=0. Cols: mat*64+nc for mat in {q,k,v,s}.
// NOTE: mat 0 (q) weights+bias are pre-scaled by 0.125 (= 1/sqrt(D)).
__global__ void k_prep(
    const float* __restrict__ Wq0, const float* __restrict__ Wk0,
    const float* __restrict__ Wv0, const float* __restrict__ Ws0,
    const float* __restrict__ Wq,  const float* __restrict__ Wk,
    const float* __restrict__ Wv,  const float* __restrict__ Ws,
    const float* __restrict__ bq0, const float* __restrict__ bk0,
    const float* __restrict__ bv0, const float* __restrict__ bs0,
    const float* __restrict__ bq,  const float* __restrict__ bk,
    const float* __restrict__ bv,  const float* __restrict__ bs)
{
    int gid = blockIdx.x*256 + threadIdx.x;
    if (gid >= 4*KTOT*256) return;
    int l   = gid / (KTOT*256);
    int rem = gid - l*(KTOT*256);
    int kk  = rem >> 8;
    int n   = rem & 255;
    int mat = n >> 6;
    int nc  = n & 63;

    __nv_bfloat16 out = __float2bfloat16_rn(0.f);
    if (kk < 192){
        int k   = kk & 63;
        int reg = kk >> 6;       // 0:hi 1:lo 2:hi
        const float* W;
        if (l == 0){
            W = (mat==0)?Wq0:(mat==1)?Wk0:(mat==2)?Wv0:Ws0;
        } else {
            const float* Wb_ = (mat==0)?Wq:(mat==1)?Wk:(mat==2)?Wv:Ws;
            W = Wb_ + (l-1)*DD*DD;
        }
        float x = W[k*64 + nc];
        if (mat == 0) x *= 0.125f;
        __nv_bfloat16 hi = __float2bfloat16_rn(x);
        if (reg == 1) out = __float2bfloat16_rn(x - __bfloat162float(hi));
        else          out = hi;
    } else if (kk == 192 || kk == 193){
        const float* b;
        if (l == 0){
            b = (mat==0)?bq0:(mat==1)?bk0:(mat==2)?bv0:bs0;
        } else {
            const float* bb = (mat==0)?bq:(mat==1)?bk:(mat==2)?bv:bs;
            b = bb + (l-1)*DD;
        }
        float x = b[nc];
        if (mat == 0) x *= 0.125f;
        __nv_bfloat16 hi = __float2bfloat16_rn(x);
        if (kk == 193) out = __float2bfloat16_rn(x - __bfloat162float(hi));
        else           out = hi;
    }
    g_Wb[(size_t)l*KTOT*256 + kk*256 + n] = out;
}

// ---------------- gemm helper phases ----------------------------------------
__device__ __forceinline__ void gemm_copyB(
    __nv_bfloat16* Bs, const __nv_bfloat16* __restrict__ Wb, int t)
{
    const uint4* gB = reinterpret_cast<const uint4*>(Wb);
    for (int i = t; i < 6656; i += 256){
        int r  = i >> 5;
        int c8 = (i & 31) << 3;
        *(uint4*)(Bs + r*B_LD + c8) = gB[i];
    }
}
__device__ __forceinline__ void gemm_fillA(
    __nv_bfloat16* As, const float* __restrict__ h, int t, int row0)
{
    #pragma unroll
    for (int i = 0; i < 8; i++){
        int idx = t + i*256;          // 0..2047 -> (r, c4)
        int r = idx >> 4, c4 = (idx & 15) * 4;
        float4 v = make_float4(0.f,0.f,0.f,0.f);
        if (row0 + r < NN) v = reinterpret_cast<const float4*>(h)[(row0+r)*16 + (c4>>2)];
        __nv_bfloat16 h0 = __float2bfloat16_rn(v.x);
        __nv_bfloat16 h1 = __float2bfloat16_rn(v.y);
        __nv_bfloat16 h2 = __float2bfloat16_rn(v.z);
        __nv_bfloat16 h3 = __float2bfloat16_rn(v.w);
        __nv_bfloat16 l0 = __float2bfloat16_rn(v.x - __bfloat162float(h0));
        __nv_bfloat16 l1 = __float2bfloat16_rn(v.y - __bfloat162float(h1));
        __nv_bfloat16 l2 = __float2bfloat16_rn(v.z - __bfloat162float(h2));
        __nv_bfloat16 l3 = __float2bfloat16_rn(v.w - __bfloat162float(h3));
        uint32_t hA = ((uint32_t)__bfloat16_as_ushort(h1) << 16) | __bfloat16_as_ushort(h0);
        uint32_t hB = ((uint32_t)__bfloat16_as_ushort(h3) << 16) | __bfloat16_as_ushort(h2);
        uint32_t lA = ((uint32_t)__bfloat16_as_ushort(l1) << 16) | __bfloat16_as_ushort(l0);
        uint32_t lB = ((uint32_t)__bfloat16_as_ushort(l3) << 16) | __bfloat16_as_ushort(l2);
        __nv_bfloat16* Ar = As + r*A_LD;
        *(uint2*)(Ar + c4)       = make_uint2(hA, hB);
        *(uint2*)(Ar + 64 + c4)  = make_uint2(hA, hB);
        *(uint2*)(Ar + 128 + c4) = make_uint2(lA, lB);
    }
}
__device__ __forceinline__ void gemm_tailA(__nv_bfloat16* As, int t)
{
    __nv_bfloat16 one  = __float2bfloat16_rn(1.0f);
    __nv_bfloat16 zero = __float2bfloat16_rn(0.0f);
    for (int idx = t; idx < 128*24; idx += 256){
        int r = idx / 24, c = idx - r*24;
        As[r*A_LD + 192 + c] = (c < 2) ? one : zero;
    }
}

// ---------------- persistent wmma bf16 fused 4-way GEMM (PDL) ----------------
__global__ void __launch_bounds__(256) k_gemm_wmma(
    const float* __restrict__ h,
    const __nv_bfloat16* __restrict__ Wb,
    int ext)
{
    extern __shared__ char sm[];
    __nv_bfloat16* As = (__nv_bfloat16*)sm;
    __nv_bfloat16* Bs = (__nv_bfloat16*)(sm + A_BYTES);
    float* stage = (float*)sm;     // 64-row k/v stage, aliases A region

    cudaTriggerProgrammaticLaunchCompletion();

    int t = threadIdx.x;
    int w = t >> 5;
    int rbase = (w & 3) * 32;
    int cbase = (w >> 2) * 128;
    int half_of_warp = (w & 3) >> 1;   // rbase 0,32 -> 0; 64,96 -> 1

    if (ext){
        gemm_fillA(As, h, t, blockIdx.x*128);
        gemm_tailA(As, t);
        cudaGridDependencySynchronize();
        gemm_copyB(Bs, Wb, t);
    } else {
        gemm_copyB(Bs, Wb, t);
        cudaGridDependencySynchronize();
    }

    for (int rb = blockIdx.x; rb < NRB; rb += gridDim.x){
        int row0 = rb*128;
        if (!(ext && rb == blockIdx.x)){
            __syncthreads();           // prior block's stage reads done
            gemm_fillA(As, h, t, row0);
            gemm_tailA(As, t);
        }
        __syncthreads();

        wmma::fragment<wmma::accumulator, 16,16,16, float> acc[2][8];
        #pragma unroll
        for (int i = 0; i < 2; i++)
            #pragma unroll
            for (int j = 0; j < 8; j++) wmma::fill_fragment(acc[i][j], 0.f);

        #pragma unroll
        for (int k = 0; k < KTOT; k += 16){
            wmma::fragment<wmma::matrix_a, 16,16,16, __nv_bfloat16, wmma::row_major> a0, a1;
            wmma::load_matrix_sync(a0, As + (rbase     )*A_LD + k, A_LD);
            wmma::load_matrix_sync(a1, As + (rbase + 16)*A_LD + k, A_LD);
            #pragma unroll
            for (int ct = 0; ct < 8; ct++){
                wmma::fragment<wmma::matrix_b, 16,16,16, __nv_bfloat16, wmma::row_major> b;
                wmma::load_matrix_sync(b, Bs + k*B_LD + cbase + ct*16, B_LD);
                wmma::mma_sync(acc[0][ct], a0, b, acc[0][ct]);
                wmma::mma_sync(acc[1][ct], a1, b, acc[1][ct]);
            }
        }

        // --- pass 1: q (mat0) and sk (mat3) straight to global fp32 --------
        #pragma unroll
        for (int rt = 0; rt < 2; rt++){
            int grow = row0 + rbase + rt*16;
            if (grow >= NN) continue;  // NN % 16 == 0: tiles never straddle
            #pragma unroll
            for (int ct = 0; ct < 8; ct++){
                int gc  = cbase + ct*16;
                int mat = gc >> 6, mc = gc & 63;
                if (mat == 0)
                    wmma::store_matrix_sync(g_q + (size_t)grow*64 + mc,
                                            acc[rt][ct], 64, wmma::mem_row_major);
                else if (mat == 3)
                    wmma::store_matrix_sync(g_sk + (size_t)grow*64 + mc,
                                            acc[rt][ct], 64, wmma::mem_row_major);
            }
        }
        __syncthreads();   // all MMA reads of As complete before staging

        // --- pass 2: k (mat1) / v (mat2) via A-region stage, 2 half-passes --
        #pragma unroll
        for (int half = 0; half < 2; half++){
            if (half_of_warp == half){
                #pragma unroll
                for (int rt = 0; rt < 2; rt++){
                    #pragma unroll
                    for (int ct = 0; ct < 8; ct++){
                        int gc  = cbase + ct*16;
                        int mat = gc >> 6;
                        if (mat == 1 || mat == 2)
                            wmma::store_matrix_sync(
                                stage + (rbase - half*64 + rt*16)*S_LD + (gc - 64),
                                acc[rt][ct], S_LD, wmma::mem_row_major);
                    }
                }
            }
            __syncthreads();
            #pragma unroll
            for (int i = 0; i < 8; i++){
                int idx = t + i*256;
                int r = idx >> 5, c4 = (idx & 31) * 4;
                int row = row0 + half*64 + r;
                if (row < NN){
                    float4 f = *(float4*)(stage + r*S_LD + c4);
                    uint32_t p0 = ((uint32_t)__bfloat16_as_ushort(__float2bfloat16_rn(f.y)) << 16)
                                |  __bfloat16_as_ushort(__float2bfloat16_rn(f.x));
                    uint32_t p1 = ((uint32_t)__bfloat16_as_ushort(__float2bfloat16_rn(f.w)) << 16)
                                |  __bfloat16_as_ushort(__float2bfloat16_rn(f.z));
                    __nv_bfloat16* dp = (c4 < 64) ? (g_kb + (size_t)row*64 + c4)
                                                  : (g_vb + (size_t)row*64 + (c4 - 64));
                    *(uint2*)dp = make_uint2(p0, p1);
                }
            }
            __syncthreads();
        }
    }
}

// ---------------- fused attention + skip + residual + LN + ReLU (PDL) -------
// warp per dst node; 4 edges/iter (8 lanes/edge, 8 dims/lane), bf16 k/v.
// No-max softmax (logits bounded). R10/R13 form — frozen (persistent,
// deeper-pipeline, and wide-edge variants all measured as regressions).
__global__ void __launch_bounds__(256) k_attn(
    const float* __restrict__ hres,
    const float* __restrict__ gamma, const float* __restrict__ beta,
    float* __restrict__ out, int addres)
{
    cudaTriggerProgrammaticLaunchCompletion();

    int warp = (blockIdx.x*blockDim.x + threadIdx.x) >> 5;
    int lane = threadIdx.x & 31;
    int g = lane >> 3;           // edge slot 0..3
    int s = lane & 7;            // dim slice: dims [s*8, s*8+8)
    int node = warp;

    // pre-sync: CSR row extent (finalized before this kernel was launched)
    int start = g_rowptr[node];
    int end   = g_rowptr[node+1];

    cudaGridDependencySynchronize();

    const float4* q4 = reinterpret_cast<const float4*>(g_q);
    float4 q0 = q4[node*16 + s*2];
    float4 q1 = q4[node*16 + s*2 + 1];

    float ssum = 0.f;
    float acc[8];
    #pragma unroll
    for (int i=0;i<8;i++) acc[i]=0.f;

    bool valid = (start + g) < end;
    int  src   = valid ? g_csrc[start + g] : 0;

    for (int j0 = start; j0 < end; j0 += 4){
        uint4 kw = *(const uint4*)(g_kb + (size_t)src*64 + s*8);
        uint4 vw = *(const uint4*)(g_vb + (size_t)src*64 + s*8);

        int  jn     = j0 + 4 + g;
        bool validn = jn < end;
        int  srcn   = validn ? g_csrc[jn] : 0;

        float2 k0 = __bfloat1622float2(*(__nv_bfloat162*)&kw.x);
        float2 k1 = __bfloat1622float2(*(__nv_bfloat162*)&kw.y);
        float2 k2 = __bfloat1622float2(*(__nv_bfloat162*)&kw.z);
        float2 k3 = __bfloat1622float2(*(__nv_bfloat162*)&kw.w);
        float p = q0.x*k0.x + q0.y*k0.y + q0.z*k1.x + q0.w*k1.y
                + q1.x*k2.x + q1.y*k2.y + q1.z*k3.x + q1.w*k3.y;
        p += __shfl_xor_sync(0xffffffffu, p, 1);
        p += __shfl_xor_sync(0xffffffffu, p, 2);
        p += __shfl_xor_sync(0xffffffffu, p, 4);

        float e = valid ? __expf(fminf(p, 80.f)) : 0.f;
        ssum += e;

        float2 v0 = __bfloat1622float2(*(__nv_bfloat162*)&vw.x);
        float2 v1 = __bfloat1622float2(*(__nv_bfloat162*)&vw.y);
        float2 v2 = __bfloat1622float2(*(__nv_bfloat162*)&vw.z);
        float2 v3 = __bfloat1622float2(*(__nv_bfloat162*)&vw.w);
        acc[0] += e*v0.x;
        acc[1] += e*v0.y;
        acc[2] += e*v1.x;
        acc[3] += e*v1.y;
        acc[4] += e*v2.x;
        acc[5] += e*v2.y;
        acc[6] += e*v3.x;
        acc[7] += e*v3.y;

        src   = srcn;
        valid = validn;
    }

    #pragma unroll
    for (int i=0;i<8;i++){
        acc[i] += __shfl_xor_sync(0xffffffffu, acc[i], 8);
        acc[i] += __shfl_xor_sync(0xffffffffu, acc[i], 16);
    }
    ssum += __shfl_xor_sync(0xffffffffu, ssum, 8);
    ssum += __shfl_xor_sync(0xffffffffu, ssum, 16);
    float inv = (ssum > 0.f) ? (1.f/ssum) : 0.f;

    const float4* sk4 = reinterpret_cast<const float4*>(g_sk);
    float4 s0 = sk4[node*16 + s*2];
    float4 s1 = sk4[node*16 + s*2 + 1];

    float o[8];
    o[0] = acc[0]*inv + s0.x;  o[1] = acc[1]*inv + s0.y;
    o[2] = acc[2]*inv + s0.z;  o[3] = acc[3]*inv + s0.w;
    o[4] = acc[4]*inv + s1.x;  o[5] = acc[5]*inv + s1.y;
    o[6] = acc[6]*inv + s1.z;  o[7] = acc[7]*inv + s1.w;

    if (addres){
        const float4* r4 = reinterpret_cast<const float4*>(hres);
        float4 r0 = r4[node*16 + s*2];
        float4 r1 = r4[node*16 + s*2 + 1];
        o[0]+=r0.x; o[1]+=r0.y; o[2]+=r0.z; o[3]+=r0.w;
        o[4]+=r1.x; o[5]+=r1.y; o[6]+=r1.z; o[7]+=r1.w;
    }

    float sum = 0.f, sq = 0.f;
    #pragma unroll
    for (int i=0;i<8;i++){ sum += o[i]; sq += o[i]*o[i]; }
    sum += __shfl_xor_sync(0xffffffffu, sum, 1);
    sum += __shfl_xor_sync(0xffffffffu, sum, 2);
    sum += __shfl_xor_sync(0xffffffffu, sum, 4);
    sq  += __shfl_xor_sync(0xffffffffu, sq, 1);
    sq  += __shfl_xor_sync(0xffffffffu, sq, 2);
    sq  += __shfl_xor_sync(0xffffffffu, sq, 4);
    float mean = sum * (1.f/64.f);
    float var  = sq  * (1.f/64.f) - mean*mean;
    float rs   = rsqrtf(var + 1e-5f);

    const float4* gm4 = reinterpret_cast<const float4*>(gamma);
    const float4* bt4 = reinterpret_cast<const float4*>(beta);
    float4 ga0 = gm4[s*2], ga1 = gm4[s*2+1];
    float4 be0 = bt4[s*2], be1 = bt4[s*2+1];

    float r[8];
    r[0] = fmaxf(0.f, (o[0]-mean)*rs*ga0.x + be0.x);
    r[1] = fmaxf(0.f, (o[1]-mean)*rs*ga0.y + be0.y);
    r[2] = fmaxf(0.f, (o[2]-mean)*rs*ga0.z + be0.z);
    r[3] = fmaxf(0.f, (o[3]-mean)*rs*ga0.w + be0.w);
    r[4] = fmaxf(0.f, (o[4]-mean)*rs*ga1.x + be1.x);
    r[5] = fmaxf(0.f, (o[5]-mean)*rs*ga1.y + be1.y);
    r[6] = fmaxf(0.f, (o[6]-mean)*rs*ga1.z + be1.z);
    r[7] = fmaxf(0.f, (o[7]-mean)*rs*ga1.w + be1.w);

    if (g == 0){
        float4* o4 = reinterpret_cast<float4*>(out);
        o4[node*16 + s*2]     = make_float4(r[0], r[1], r[2], r[3]);
        o4[node*16 + s*2 + 1] = make_float4(r[4], r[5], r[6], r[7]);
    }
}

// ---------------- PDL launch helpers ----------------------------------------
static void launch_gemm_pdl(const float* h, const __nv_bfloat16* wb, int ext){
    cudaLaunchConfig_t cfg = {};
    cfg.gridDim = dim3(GEMM_GRID);
    cfg.blockDim = dim3(256);
    cfg.dynamicSmemBytes = GEMM_SMEM;
    cfg.stream = 0;
    cudaLaunchAttribute at[1];
    at[0].id = cudaLaunchAttributeProgrammaticStreamSerialization;
    at[0].val.programmaticStreamSerializationAllowed = 1;
    cfg.attrs = at;
    cfg.numAttrs = 1;
    cudaLaunchKernelEx(&cfg, k_gemm_wmma, h, wb, ext);
}
static void launch_attn_pdl(const float* hres, const float* gm, const float* bt,
                            float* out, int addres){
    cudaLaunchConfig_t cfg = {};
    cfg.gridDim = dim3((NN*32 + 255) / 256);
    cfg.blockDim = dim3(256);
    cfg.dynamicSmemBytes = 0;
    cfg.stream = 0;
    cudaLaunchAttribute at[1];
    at[0].id = cudaLaunchAttributeProgrammaticStreamSerialization;
    at[0].val.programmaticStreamSerializationAllowed = 1;
    cfg.attrs = at;
    cfg.numAttrs = 1;
    cudaLaunchKernelEx(&cfg, k_attn, hres, gm, bt, out, addres);
}

extern "C" void kernel_launch(void* const* d_in, const int* in_sizes, int n_in,
                              void* d_out, int out_size)
{
    const float* x    = (const float*)d_in[0];
    const int*   ei   = (const int*)  d_in[1];
    const float* Wq0  = (const float*)d_in[2];
    const float* bq0  = (const float*)d_in[3];
    const float* Wk0  = (const float*)d_in[4];
    const float* bk0  = (const float*)d_in[5];
    const float* Wv0  = (const float*)d_in[6];
    const float* bv0  = (const float*)d_in[7];
    const float* Ws0  = (const float*)d_in[8];
    const float* bs0  = (const float*)d_in[9];
    const float* ln0g = (const float*)d_in[10];
    const float* ln0b = (const float*)d_in[11];
    const float* Wq   = (const float*)d_in[12];
    const float* bq   = (const float*)d_in[13];
    const float* Wk   = (const float*)d_in[14];
    const float* bk   = (const float*)d_in[15];
    const float* Wv   = (const float*)d_in[16];
    const float* bv   = (const float*)d_in[17];
    const float* Ws   = (const float*)d_in[18];
    const float* bs   = (const float*)d_in[19];
    const float* lng  = (const float*)d_in[20];
    const float* lnb  = (const float*)d_in[21];
    float* out = (float*)d_out;

    const int*  srcp = ei;
    const int*  dstp = ei + EE;
    const int4* dst4 = (const int4*)(ei + EE);

    float *bufA = nullptr, *bufB = nullptr;
    __nv_bfloat16* wb = nullptr;
    cudaGetSymbolAddress((void**)&bufA, g_bufA);
    cudaGetSymbolAddress((void**)&bufB, g_bufB);
    cudaGetSymbolAddress((void**)&wb, g_Wb);

    cudaFuncSetAttribute(k_gemm_wmma, cudaFuncAttributeMaxDynamicSharedMemorySize,
                         GEMM_SMEM);

    // side stream + fork/join events, created once (first call is the
    // non-captured correctness run; capture sees only launches/events)
    static cudaStream_t s2 = nullptr;
    static cudaEvent_t  evF = nullptr, evJ = nullptr;
    if (s2 == nullptr){
        cudaStreamCreateWithFlags(&s2, cudaStreamNonBlocking);
        cudaEventCreateWithFlags(&evF, cudaEventDisableTiming);
        cudaEventCreateWithFlags(&evJ, cudaEventDisableTiming);
    }

    // fork: CSR build on s2 (4 kernels); weight prep + gemm0 on main stream.
    // g_deg is pre-zeroed (zero-init at load; scan1 resets it every call).
    cudaEventRecord(evF, 0);
    cudaStreamWaitEvent(s2, evF, 0);
    k_hist    <<<(EE/4 + 255)/256, 256, 0, s2>>>(dst4);
    k_scan1   <<<NCHUNK, 1024, 0, s2>>>();
    k_scan3   <<<NCHUNK, 1024, 0, s2>>>();
    k_scatter <<<(EE + 255)/256, 256, 0, s2>>>(srcp, dstp);
    cudaEventRecord(evJ, s2);

    k_prep<<<(4*KTOT*256 + 255)/256, 256>>>(Wq0, Wk0, Wv0, Ws0, Wq, Wk, Wv, Ws,
                                            bq0, bk0, bv0, bs0, bq, bk, bv, bs);
    // gemm0: PDL with ext=1 — first-block A fill (from harness input x) runs
    // pre-sync; B copy (k_prep output) runs post-gridsync.
    launch_gemm_pdl(x, wb, 1);

    // join: attention needs the CSR
    cudaStreamWaitEvent(0, evJ, 0);

    // layer 0 (input projection, no residual) — PDL vs gemm0
    launch_attn_pdl(x /*unused*/, ln0g, ln0b, bufA, 0);

    // 3 dynamics layers (with residual); final one writes d_out — all PDL
    const float* ins[3]  = {bufA, bufB, bufA};
    float*       outs[3] = {bufB, bufA, out};
    for (int i = 0; i < 3; i++){
        launch_gemm_pdl(ins[i], wb + (size_t)(i+1)*KTOT*256, 0);
        launch_attn_pdl(ins[i], lng + i*DD, lnb + i*DD, outs[i], 1);
    }
}

// round 17
// speedup vs baseline: 1.0981x; 1.0212x over previous
#include <cuda_runtime.h>
#include <cuda_bf16.h>
#include <mma.h>
#include <cstdint>

using namespace nvcuda;

#define NN 50000
#define EE 1000000
#define DD 64

// extended-K GEMM geometry: [hi|hi|lo] (192) + bias_hi + bias_lo + pad = 208
#define KTOT 208
#define A_LD 216      // bf16 elements per A row in smem
#define B_LD 264      // bf16 elements per B row in smem
#define A_BYTES (128*A_LD*2)          // 55296
#define B_BYTES (KTOT*B_LD*2)         // 109824
#define GEMM_SMEM (A_BYTES + B_BYTES) // 165120
#define S_LD 132      // fp32 stage ld (64-row half, lives in A region)
#define GEMM_GRID 152 // persistent CTAs (GB300: 152 SMs)
#define NRB ((NN + 127) / 128)        // 391 row blocks

#define NCHUNK 49     // ceil(NN/1024)

// ---------------- scratch (device globals; no allocation allowed) ----------
__device__ float g_bufA[NN*DD];
__device__ float g_bufB[NN*DD];
__device__ float g_q [NN*DD];
__device__ float g_sk[NN*DD];
__device__ __nv_bfloat16 g_kvb[NN*128];   // interleaved: [node][0..63]=k, [64..127]=v
__device__ int   g_deg[NN];           // zero-init; scan1 re-zeroes after use
__device__ int   g_rowptr[NN+1];
__device__ int   g_cursor[NN];
__device__ int   g_csrc[EE];
__device__ int   g_bsum[64];
// prepped weights: 4 layer-sets x [KTOT rows x 256 cols] bf16
__device__ __nv_bfloat16 g_Wb[4*KTOT*256];

// ---------------- CSR build (by dst) ---------------------------------------
// g_deg is zero before every call: zero-initialized at load, and k_scan1
// resets each element after consuming it (deterministic across replays).
__global__ void k_hist(const int4* __restrict__ dst4){
    int i = blockIdx.x*blockDim.x + threadIdx.x;
    if (i < EE/4){
        int4 d = dst4[i];
        atomicAdd(&g_deg[d.x], 1);
        atomicAdd(&g_deg[d.y], 1);
        atomicAdd(&g_deg[d.z], 1);
        atomicAdd(&g_deg[d.w], 1);
    }
}
// phase 1: per-block local exclusive scan -> rowptr(local), block sums;
// also resets g_deg for the next replay.
__global__ void k_scan1(){
    __shared__ int wsum[32];
    int b = blockIdx.x, t = threadIdx.x, lane = t & 31, w = t >> 5;
    int i = b*1024 + t;
    int v = (i < NN) ? g_deg[i] : 0;
    if (i < NN) g_deg[i] = 0;                 // reset for next call
    int x = v;
    #pragma unroll
    for (int off = 1; off < 32; off <<= 1){
        int y = __shfl_up_sync(0xffffffffu, x, off);
        if (lane >= off) x += y;
    }
    if (lane == 31) wsum[w] = x;
    __syncthreads();
    if (w == 0){
        int s = wsum[lane];
        #pragma unroll
        for (int off = 1; off < 32; off <<= 1){
            int y = __shfl_up_sync(0xffffffffu, s, off);
            if (lane >= off) s += y;
        }
        wsum[lane] = s;
    }
    __syncthreads();
    int incl = x + ((w > 0) ? wsum[w-1] : 0);
    if (i < NN) g_rowptr[i] = incl - v;       // local exclusive
    if (t == 1023) g_bsum[b] = incl;          // block total
}
// phase 2+3 fused: every block redundantly scans the 49 block sums in smem
// (cheap), applies its own offset, materializes rowptr/cursor.
__global__ void k_scan3(){
    __shared__ int s[64];
    int t = threadIdx.x;
    if (t < 64) s[t] = (t < NCHUNK) ? g_bsum[t] : 0;
    __syncthreads();
    #pragma unroll
    for (int off = 1; off < 64; off <<= 1){
        int y = (t < 64 && t >= off) ? s[t-off] : 0;
        __syncthreads();
        if (t < 64) s[t] += y;
        __syncthreads();
    }
    int bo = (blockIdx.x > 0) ? s[blockIdx.x - 1] : 0;   // exclusive offset
    int i = blockIdx.x*1024 + t;
    if (i < NN){
        int r = g_rowptr[i] + bo;
        g_rowptr[i] = r;
        g_cursor[i] = r;
    }
    if (blockIdx.x == 0 && t == 0) g_rowptr[NN] = s[63]; // grand total
}
__global__ void k_scatter(const int* __restrict__ src, const int* __restrict__ dst){
    int e = blockIdx.x*blockDim.x + threadIdx.x;
    if (e < EE){
        int pos = atomicAdd(&g_cursor[dst[e]], 1);
        g_csrc[pos] = src[e];
    }
}

// ---------------- weight prep ------------------------------------------------
// g_Wb[l] rows: [0,64)=W_hi, [64,128)=W_lo, [128,192)=W_hi, 192=bias_hi,
// 193=bias_lo, [194,208)=0. Cols: mat*64+nc for mat in {q,k,v,s}.
// NOTE: mat 0 (q) weights+bias are pre-scaled by 0.125 (= 1/sqrt(D)).
__global__ void k_prep(
    const float* __restrict__ Wq0, const float* __restrict__ Wk0,
    const float* __restrict__ Wv0, const float* __restrict__ Ws0,
    const float* __restrict__ Wq,  const float* __restrict__ Wk,
    const float* __restrict__ Wv,  const float* __restrict__ Ws,
    const float* __restrict__ bq0, const float* __restrict__ bk0,
    const float* __restrict__ bv0, const float* __restrict__ bs0,
    const float* __restrict__ bq,  const float* __restrict__ bk,
    const float* __restrict__ bv,  const float* __restrict__ bs)
{
    int gid = blockIdx.x*256 + threadIdx.x;
    if (gid >= 4*KTOT*256) return;
    int l   = gid / (KTOT*256);
    int rem = gid - l*(KTOT*256);
    int kk  = rem >> 8;
    int n   = rem & 255;
    int mat = n >> 6;
    int nc  = n & 63;

    __nv_bfloat16 out = __float2bfloat16_rn(0.f);
    if (kk < 192){
        int k   = kk & 63;
        int reg = kk >> 6;       // 0:hi 1:lo 2:hi
        const float* W;
        if (l == 0){
            W = (mat==0)?Wq0:(mat==1)?Wk0:(mat==2)?Wv0:Ws0;
        } else {
            const float* Wb_ = (mat==0)?Wq:(mat==1)?Wk:(mat==2)?Wv:Ws;
            W = Wb_ + (l-1)*DD*DD;
        }
        float x = W[k*64 + nc];
        if (mat == 0) x *= 0.125f;
        __nv_bfloat16 hi = __float2bfloat16_rn(x);
        if (reg == 1) out = __float2bfloat16_rn(x - __bfloat162float(hi));
        else          out = hi;
    } else if (kk == 192 || kk == 193){
        const float* b;
        if (l == 0){
            b = (mat==0)?bq0:(mat==1)?bk0:(mat==2)?bv0:bs0;
        } else {
            const float* bb = (mat==0)?bq:(mat==1)?bk:(mat==2)?bv:bs;
            b = bb + (l-1)*DD;
        }
        float x = b[nc];
        if (mat == 0) x *= 0.125f;
        __nv_bfloat16 hi = __float2bfloat16_rn(x);
        if (kk == 193) out = __float2bfloat16_rn(x - __bfloat162float(hi));
        else           out = hi;
    }
    g_Wb[(size_t)l*KTOT*256 + kk*256 + n] = out;
}

// ---------------- gemm helper phases ----------------------------------------
__device__ __forceinline__ void gemm_copyB(
    __nv_bfloat16* Bs, const __nv_bfloat16* __restrict__ Wb, int t)
{
    const uint4* gB = reinterpret_cast<const uint4*>(Wb);
    for (int i = t; i < 6656; i += 256){
        int r  = i >> 5;
        int c8 = (i & 31) << 3;
        *(uint4*)(Bs + r*B_LD + c8) = gB[i];
    }
}
__device__ __forceinline__ void gemm_fillA(
    __nv_bfloat16* As, const float* __restrict__ h, int t, int row0)
{
    #pragma unroll
    for (int i = 0; i < 8; i++){
        int idx = t + i*256;          // 0..2047 -> (r, c4)
        int r = idx >> 4, c4 = (idx & 15) * 4;
        float4 v = make_float4(0.f,0.f,0.f,0.f);
        if (row0 + r < NN) v = reinterpret_cast<const float4*>(h)[(row0+r)*16 + (c4>>2)];
        __nv_bfloat16 h0 = __float2bfloat16_rn(v.x);
        __nv_bfloat16 h1 = __float2bfloat16_rn(v.y);
        __nv_bfloat16 h2 = __float2bfloat16_rn(v.z);
        __nv_bfloat16 h3 = __float2bfloat16_rn(v.w);
        __nv_bfloat16 l0 = __float2bfloat16_rn(v.x - __bfloat162float(h0));
        __nv_bfloat16 l1 = __float2bfloat16_rn(v.y - __bfloat162float(h1));
        __nv_bfloat16 l2 = __float2bfloat16_rn(v.z - __bfloat162float(h2));
        __nv_bfloat16 l3 = __float2bfloat16_rn(v.w - __bfloat162float(h3));
        uint32_t hA = ((uint32_t)__bfloat16_as_ushort(h1) << 16) | __bfloat16_as_ushort(h0);
        uint32_t hB = ((uint32_t)__bfloat16_as_ushort(h3) << 16) | __bfloat16_as_ushort(h2);
        uint32_t lA = ((uint32_t)__bfloat16_as_ushort(l1) << 16) | __bfloat16_as_ushort(l0);
        uint32_t lB = ((uint32_t)__bfloat16_as_ushort(l3) << 16) | __bfloat16_as_ushort(l2);
        __nv_bfloat16* Ar = As + r*A_LD;
        *(uint2*)(Ar + c4)       = make_uint2(hA, hB);
        *(uint2*)(Ar + 64 + c4)  = make_uint2(hA, hB);
        *(uint2*)(Ar + 128 + c4) = make_uint2(lA, lB);
    }
}
__device__ __forceinline__ void gemm_tailA(__nv_bfloat16* As, int t)
{
    __nv_bfloat16 one  = __float2bfloat16_rn(1.0f);
    __nv_bfloat16 zero = __float2bfloat16_rn(0.0f);
    for (int idx = t; idx < 128*24; idx += 256){
        int r = idx / 24, c = idx - r*24;
        As[r*A_LD + 192 + c] = (c < 2) ? one : zero;
    }
}

// ---------------- persistent wmma bf16 fused 4-way GEMM (PDL) ----------------
__global__ void __launch_bounds__(256) k_gemm_wmma(
    const float* __restrict__ h,
    const __nv_bfloat16* __restrict__ Wb,
    int ext)
{
    extern __shared__ char sm[];
    __nv_bfloat16* As = (__nv_bfloat16*)sm;
    __nv_bfloat16* Bs = (__nv_bfloat16*)(sm + A_BYTES);
    float* stage = (float*)sm;     // 64-row k/v stage, aliases A region

    cudaTriggerProgrammaticLaunchCompletion();

    int t = threadIdx.x;
    int w = t >> 5;
    int rbase = (w & 3) * 32;
    int cbase = (w >> 2) * 128;
    int half_of_warp = (w & 3) >> 1;   // rbase 0,32 -> 0; 64,96 -> 1

    if (ext){
        gemm_fillA(As, h, t, blockIdx.x*128);
        gemm_tailA(As, t);
        cudaGridDependencySynchronize();
        gemm_copyB(Bs, Wb, t);
    } else {
        gemm_copyB(Bs, Wb, t);
        cudaGridDependencySynchronize();
    }

    for (int rb = blockIdx.x; rb < NRB; rb += gridDim.x){
        int row0 = rb*128;
        if (!(ext && rb == blockIdx.x)){
            __syncthreads();           // prior block's stage reads done
            gemm_fillA(As, h, t, row0);
            gemm_tailA(As, t);
        }
        __syncthreads();

        wmma::fragment<wmma::accumulator, 16,16,16, float> acc[2][8];
        #pragma unroll
        for (int i = 0; i < 2; i++)
            #pragma unroll
            for (int j = 0; j < 8; j++) wmma::fill_fragment(acc[i][j], 0.f);

        #pragma unroll
        for (int k = 0; k < KTOT; k += 16){
            wmma::fragment<wmma::matrix_a, 16,16,16, __nv_bfloat16, wmma::row_major> a0, a1;
            wmma::load_matrix_sync(a0, As + (rbase     )*A_LD + k, A_LD);
            wmma::load_matrix_sync(a1, As + (rbase + 16)*A_LD + k, A_LD);
            #pragma unroll
            for (int ct = 0; ct < 8; ct++){
                wmma::fragment<wmma::matrix_b, 16,16,16, __nv_bfloat16, wmma::row_major> b;
                wmma::load_matrix_sync(b, Bs + k*B_LD + cbase + ct*16, B_LD);
                wmma::mma_sync(acc[0][ct], a0, b, acc[0][ct]);
                wmma::mma_sync(acc[1][ct], a1, b, acc[1][ct]);
            }
        }

        // --- pass 1: q (mat0) and sk (mat3) straight to global fp32 --------
        #pragma unroll
        for (int rt = 0; rt < 2; rt++){
            int grow = row0 + rbase + rt*16;
            if (grow >= NN) continue;  // NN % 16 == 0: tiles never straddle
            #pragma unroll
            for (int ct = 0; ct < 8; ct++){
                int gc  = cbase + ct*16;
                int mat = gc >> 6, mc = gc & 63;
                if (mat == 0)
                    wmma::store_matrix_sync(g_q + (size_t)grow*64 + mc,
                                            acc[rt][ct], 64, wmma::mem_row_major);
                else if (mat == 3)
                    wmma::store_matrix_sync(g_sk + (size_t)grow*64 + mc,
                                            acc[rt][ct], 64, wmma::mem_row_major);
            }
        }
        __syncthreads();   // all MMA reads of As complete before staging

        // --- pass 2: k (mat1) / v (mat2) via A-region stage, 2 half-passes --
        // stage cols 0..63 = k, 64..127 = v — matches g_kvb layout directly.
        #pragma unroll
        for (int half = 0; half < 2; half++){
            if (half_of_warp == half){
                #pragma unroll
                for (int rt = 0; rt < 2; rt++){
                    #pragma unroll
                    for (int ct = 0; ct < 8; ct++){
                        int gc  = cbase + ct*16;
                        int mat = gc >> 6;
                        if (mat == 1 || mat == 2)
                            wmma::store_matrix_sync(
                                stage + (rbase - half*64 + rt*16)*S_LD + (gc - 64),
                                acc[rt][ct], S_LD, wmma::mem_row_major);
                    }
                }
            }
            __syncthreads();
            #pragma unroll
            for (int i = 0; i < 8; i++){
                int idx = t + i*256;
                int r = idx >> 5, c4 = (idx & 31) * 4;
                int row = row0 + half*64 + r;
                if (row < NN){
                    float4 f = *(float4*)(stage + r*S_LD + c4);
                    uint32_t p0 = ((uint32_t)__bfloat16_as_ushort(__float2bfloat16_rn(f.y)) << 16)
                                |  __bfloat16_as_ushort(__float2bfloat16_rn(f.x));
                    uint32_t p1 = ((uint32_t)__bfloat16_as_ushort(__float2bfloat16_rn(f.w)) << 16)
                                |  __bfloat16_as_ushort(__float2bfloat16_rn(f.z));
                    *(uint2*)(g_kvb + (size_t)row*128 + c4) = make_uint2(p0, p1);
                }
            }
            __syncthreads();
        }
    }
}

// ---------------- fused attention + skip + residual + LN + ReLU (PDL) -------
// warp per dst node; 4 edges/iter (8 lanes/edge, 8 dims/lane), bf16 k/v
// interleaved per node (one contiguous 256B block per edge). No-max softmax
// (logits bounded). R10/R13 loop form — frozen.
__global__ void __launch_bounds__(256) k_attn(
    const float* __restrict__ hres,
    const float* __restrict__ gamma, const float* __restrict__ beta,
    float* __restrict__ out, int addres)
{
    cudaTriggerProgrammaticLaunchCompletion();

    int warp = (blockIdx.x*blockDim.x + threadIdx.x) >> 5;
    int lane = threadIdx.x & 31;
    int g = lane >> 3;           // edge slot 0..3
    int s = lane & 7;            // dim slice: dims [s*8, s*8+8)
    int node = warp;

    // pre-sync: CSR row extent (finalized before this kernel was launched)
    int start = g_rowptr[node];
    int end   = g_rowptr[node+1];

    cudaGridDependencySynchronize();

    const float4* q4 = reinterpret_cast<const float4*>(g_q);
    float4 q0 = q4[node*16 + s*2];
    float4 q1 = q4[node*16 + s*2 + 1];

    float ssum = 0.f;
    float acc[8];
    #pragma unroll
    for (int i=0;i<8;i++) acc[i]=0.f;

    bool valid = (start + g) < end;
    int  src   = valid ? g_csrc[start + g] : 0;

    for (int j0 = start; j0 < end; j0 += 4){
        const __nv_bfloat16* kvp = g_kvb + (size_t)src*128 + s*8;
        uint4 kw = *(const uint4*)kvp;          // k dims [s*8, s*8+8)
        uint4 vw = *(const uint4*)(kvp + 64);   // v dims (same 256B block)

        int  jn     = j0 + 4 + g;
        bool validn = jn < end;
        int  srcn   = validn ? g_csrc[jn] : 0;

        float2 k0 = __bfloat1622float2(*(__nv_bfloat162*)&kw.x);
        float2 k1 = __bfloat1622float2(*(__nv_bfloat162*)&kw.y);
        float2 k2 = __bfloat1622float2(*(__nv_bfloat162*)&kw.z);
        float2 k3 = __bfloat1622float2(*(__nv_bfloat162*)&kw.w);
        float p = q0.x*k0.x + q0.y*k0.y + q0.z*k1.x + q0.w*k1.y
                + q1.x*k2.x + q1.y*k2.y + q1.z*k3.x + q1.w*k3.y;
        p += __shfl_xor_sync(0xffffffffu, p, 1);
        p += __shfl_xor_sync(0xffffffffu, p, 2);
        p += __shfl_xor_sync(0xffffffffu, p, 4);

        float e = valid ? __expf(fminf(p, 80.f)) : 0.f;
        ssum += e;

        float2 v0 = __bfloat1622float2(*(__nv_bfloat162*)&vw.x);
        float2 v1 = __bfloat1622float2(*(__nv_bfloat162*)&vw.y);
        float2 v2 = __bfloat1622float2(*(__nv_bfloat162*)&vw.z);
        float2 v3 = __bfloat1622float2(*(__nv_bfloat162*)&vw.w);
        acc[0] += e*v0.x;
        acc[1] += e*v0.y;
        acc[2] += e*v1.x;
        acc[3] += e*v1.y;
        acc[4] += e*v2.x;
        acc[5] += e*v2.y;
        acc[6] += e*v3.x;
        acc[7] += e*v3.y;

        src   = srcn;
        valid = validn;
    }

    #pragma unroll
    for (int i=0;i<8;i++){
        acc[i] += __shfl_xor_sync(0xffffffffu, acc[i], 8);
        acc[i] += __shfl_xor_sync(0xffffffffu, acc[i], 16);
    }
    ssum += __shfl_xor_sync(0xffffffffu, ssum, 8);
    ssum += __shfl_xor_sync(0xffffffffu, ssum, 16);
    float inv = (ssum > 0.f) ? (1.f/ssum) : 0.f;

    const float4* sk4 = reinterpret_cast<const float4*>(g_sk);
    float4 s0 = sk4[node*16 + s*2];
    float4 s1 = sk4[node*16 + s*2 + 1];

    float o[8];
    o[0] = acc[0]*inv + s0.x;  o[1] = acc[1]*inv + s0.y;
    o[2] = acc[2]*inv + s0.z;  o[3] = acc[3]*inv + s0.w;
    o[4] = acc[4]*inv + s1.x;  o[5] = acc[5]*inv + s1.y;
    o[6] = acc[6]*inv + s1.z;  o[7] = acc[7]*inv + s1.w;

    if (addres){
        const float4* r4 = reinterpret_cast<const float4*>(hres);
        float4 r0 = r4[node*16 + s*2];
        float4 r1 = r4[node*16 + s*2 + 1];
        o[0]+=r0.x; o[1]+=r0.y; o[2]+=r0.z; o[3]+=r0.w;
        o[4]+=r1.x; o[5]+=r1.y; o[6]+=r1.z; o[7]+=r1.w;
    }

    float sum = 0.f, sq = 0.f;
    #pragma unroll
    for (int i=0;i<8;i++){ sum += o[i]; sq += o[i]*o[i]; }
    sum += __shfl_xor_sync(0xffffffffu, sum, 1);
    sum += __shfl_xor_sync(0xffffffffu, sum, 2);
    sum += __shfl_xor_sync(0xffffffffu, sum, 4);
    sq  += __shfl_xor_sync(0xffffffffu, sq, 1);
    sq  += __shfl_xor_sync(0xffffffffu, sq, 2);
    sq  += __shfl_xor_sync(0xffffffffu, sq, 4);
    float mean = sum * (1.f/64.f);
    float var  = sq  * (1.f/64.f) - mean*mean;
    float rs   = rsqrtf(var + 1e-5f);

    const float4* gm4 = reinterpret_cast<const float4*>(gamma);
    const float4* bt4 = reinterpret_cast<const float4*>(beta);
    float4 ga0 = gm4[s*2], ga1 = gm4[s*2+1];
    float4 be0 = bt4[s*2], be1 = bt4[s*2+1];

    float r[8];
    r[0] = fmaxf(0.f, (o[0]-mean)*rs*ga0.x + be0.x);
    r[1] = fmaxf(0.f, (o[1]-mean)*rs*ga0.y + be0.y);
    r[2] = fmaxf(0.f, (o[2]-mean)*rs*ga0.z + be0.z);
    r[3] = fmaxf(0.f, (o[3]-mean)*rs*ga0.w + be0.w);
    r[4] = fmaxf(0.f, (o[4]-mean)*rs*ga1.x + be1.x);
    r[5] = fmaxf(0.f, (o[5]-mean)*rs*ga1.y + be1.y);
    r[6] = fmaxf(0.f, (o[6]-mean)*rs*ga1.z + be1.z);
    r[7] = fmaxf(0.f, (o[7]-mean)*rs*ga1.w + be1.w);

    if (g == 0){
        float4* o4 = reinterpret_cast<float4*>(out);
        o4[node*16 + s*2]     = make_float4(r[0], r[1], r[2], r[3]);
        o4[node*16 + s*2 + 1] = make_float4(r[4], r[5], r[6], r[7]);
    }
}

// ---------------- PDL launch helpers ----------------------------------------
static void launch_gemm_pdl(const float* h, const __nv_bfloat16* wb, int ext){
    cudaLaunchConfig_t cfg = {};
    cfg.gridDim = dim3(GEMM_GRID);
    cfg.blockDim = dim3(256);
    cfg.dynamicSmemBytes = GEMM_SMEM;
    cfg.stream = 0;
    cudaLaunchAttribute at[1];
    at[0].id = cudaLaunchAttributeProgrammaticStreamSerialization;
    at[0].val.programmaticStreamSerializationAllowed = 1;
    cfg.attrs = at;
    cfg.numAttrs = 1;
    cudaLaunchKernelEx(&cfg, k_gemm_wmma, h, wb, ext);
}
static void launch_attn_pdl(const float* hres, const float* gm, const float* bt,
                            float* out, int addres){
    cudaLaunchConfig_t cfg = {};
    cfg.gridDim = dim3((NN*32 + 255) / 256);
    cfg.blockDim = dim3(256);
    cfg.dynamicSmemBytes = 0;
    cfg.stream = 0;
    cudaLaunchAttribute at[1];
    at[0].id = cudaLaunchAttributeProgrammaticStreamSerialization;
    at[0].val.programmaticStreamSerializationAllowed = 1;
    cfg.attrs = at;
    cfg.numAttrs = 1;
    cudaLaunchKernelEx(&cfg, k_attn, hres, gm, bt, out, addres);
}

extern "C" void kernel_launch(void* const* d_in, const int* in_sizes, int n_in,
                              void* d_out, int out_size)
{
    const float* x    = (const float*)d_in[0];
    const int*   ei   = (const int*)  d_in[1];
    const float* Wq0  = (const float*)d_in[2];
    const float* bq0  = (const float*)d_in[3];
    const float* Wk0  = (const float*)d_in[4];
    const float* bk0  = (const float*)d_in[5];
    const float* Wv0  = (const float*)d_in[6];
    const float* bv0  = (const float*)d_in[7];
    const float* Ws0  = (const float*)d_in[8];
    const float* bs0  = (const float*)d_in[9];
    const float* ln0g = (const float*)d_in[10];
    const float* ln0b = (const float*)d_in[11];
    const float* Wq   = (const float*)d_in[12];
    const float* bq   = (const float*)d_in[13];
    const float* Wk   = (const float*)d_in[14];
    const float* bk   = (const float*)d_in[15];
    const float* Wv   = (const float*)d_in[16];
    const float* bv   = (const float*)d_in[17];
    const float* Ws   = (const float*)d_in[18];
    const float* bs   = (const float*)d_in[19];
    const float* lng  = (const float*)d_in[20];
    const float* lnb  = (const float*)d_in[21];
    float* out = (float*)d_out;

    const int*  srcp = ei;
    const int*  dstp = ei + EE;
    const int4* dst4 = (const int4*)(ei + EE);

    float *bufA = nullptr, *bufB = nullptr;
    __nv_bfloat16* wb = nullptr;
    cudaGetSymbolAddress((void**)&bufA, g_bufA);
    cudaGetSymbolAddress((void**)&bufB, g_bufB);
    cudaGetSymbolAddress((void**)&wb, g_Wb);

    cudaFuncSetAttribute(k_gemm_wmma, cudaFuncAttributeMaxDynamicSharedMemorySize,
                         GEMM_SMEM);

    // side stream + fork/join events, created once (first call is the
    // non-captured correctness run; capture sees only launches/events)
    static cudaStream_t s2 = nullptr;
    static cudaEvent_t  evF = nullptr, evJ = nullptr;
    if (s2 == nullptr){
        cudaStreamCreateWithFlags(&s2, cudaStreamNonBlocking);
        cudaEventCreateWithFlags(&evF, cudaEventDisableTiming);
        cudaEventCreateWithFlags(&evJ, cudaEventDisableTiming);
    }

    // fork: CSR build on s2 (4 kernels); weight prep + gemm0 on main stream.
    // g_deg is pre-zeroed (zero-init at load; scan1 resets it every call).
    cudaEventRecord(evF, 0);
    cudaStreamWaitEvent(s2, evF, 0);
    k_hist    <<<(EE/4 + 255)/256, 256, 0, s2>>>(dst4);
    k_scan1   <<<NCHUNK, 1024, 0, s2>>>();
    k_scan3   <<<NCHUNK, 1024, 0, s2>>>();
    k_scatter <<<(EE + 255)/256, 256, 0, s2>>>(srcp, dstp);
    cudaEventRecord(evJ, s2);

    k_prep<<<(4*KTOT*256 + 255)/256, 256>>>(Wq0, Wk0, Wv0, Ws0, Wq, Wk, Wv, Ws,
                                            bq0, bk0, bv0, bs0, bq, bk, bv, bs);
    // gemm0: PDL with ext=1 — first-block A fill (from harness input x) runs
    // pre-sync; B copy (k_prep output) runs post-gridsync.
    launch_gemm_pdl(x, wb, 1);

    // join: attention needs the CSR
    cudaStreamWaitEvent(0, evJ, 0);

    // layer 0 (input projection, no residual) — PDL vs gemm0
    launch_attn_pdl(x /*unused*/, ln0g, ln0b, bufA, 0);

    // 3 dynamics layers (with residual); final one writes d_out — all PDL
    const float* ins[3]  = {bufA, bufB, bufA};
    float*       outs[3] = {bufB, bufA, out};
    for (int i = 0; i < 3; i++){
        launch_gemm_pdl(ins[i], wb + (size_t)(i+1)*KTOT*256, 0);
        launch_attn_pdl(ins[i], lng + i*DD, lnb + i*DD, outs[i], 1);
    }
}